// round 1
// baseline (speedup 1.0000x reference)
#include <cuda_runtime.h>

// Global accumulator (no allocation allowed).
__device__ double g_acc;

__global__ void zero_kernel() { g_acc = 0.0; }
__global__ void final_kernel(float* out) { out[0] = (float)g_acc; }

struct AnchorParams {
    // per-anchor a in [0,3): scale = anchor/416, inv = 416/anchor
    float s_aw[3], s_ah[3], i_aw[3], i_ah[3];
};

__global__ __launch_bounds__(256)
void yolo_layer_kernel(const float* __restrict__ pred,
                       const float* __restrict__ ytr,
                       const float* __restrict__ target,
                       int B, int H, int W, float invW, float invH,
                       AnchorParams ap)
{
    const int idx = blockIdx.x * blockDim.x + threadIdx.x;
    const int total = B * 3 * H * W;
    float loss = 0.f;

    if (idx < total) {
        const int x = idx % W;
        const int y = (idx / W) % H;
        const int a = (idx / (W * H)) % 3;
        const int b = idx / (W * H * 3);
        const int cs = H * W;

        const float* __restrict__ t85 = ytr + (size_t)idx * 85;
        const float* __restrict__ p   = pred + ((size_t)(b * 255 + a * 85) * H + y) * W + x;

        const float s_aw = ap.s_aw[a], s_ah = ap.s_ah[a];
        const float i_aw = ap.i_aw[a], i_ah = ap.i_ah[a];

        const float r0 = p[0];
        const float r1 = p[cs];
        const float r2 = p[2 * cs];
        const float r3 = p[3 * cs];
        const float r4 = p[4 * cs];
        const float t0 = t85[0], t1 = t85[1], t2 = t85[2], t3 = t85[3], om = t85[4];

        const float gx = (float)x, gy = (float)y;

        // softplus(-r) = log(1 + exp(-r));  bce(sigmoid(r), t) = sp + (1-t)*r
        const float e0 = __expf(-r0), e1 = __expf(-r1), e4 = __expf(-r4);
        const float sp0 = __logf(1.f + e0);
        const float sp1 = __logf(1.f + e1);
        const float sp4 = __logf(1.f + e4);

        // ---- xy loss ----
        const float truex = t0 * (float)H - gx;   // ref uses [h, w] order
        const float truey = t1 * (float)W - gy;
        const float bce_x = sp0 + (1.f - truex) * r0;
        const float bce_y = sp1 + (1.f - truey) * r1;
        const float ls = 2.f - t2 * t3;
        loss += om * ls * (bce_x + bce_y);

        // ---- wh loss ----
        float twh = __logf(t2 * i_aw);
        float thh = __logf(t3 * i_ah);
        if (!(om > 0.f)) { twh = 0.f; thh = 0.f; }
        const float dw = r2 - twh, dh = r3 - thh;
        loss += om * ls * 0.5f * (dw * dw + dh * dh);

        // ---- predicted box for IoU ----
        const float sx = __fdividef(1.f, 1.f + e0);
        const float sy = __fdividef(1.f, 1.f + e1);
        const float bx = (sx + gx) * invW;
        const float by = (sy + gy) * invH;
        const float bw = __expf(r2) * s_aw;
        const float bh = __expf(r3) * s_ah;
        const float b1minx = bx - 0.5f * bw, b1maxx = bx + 0.5f * bw;
        const float b1miny = by - 0.5f * bh, b1maxy = by + 0.5f * bh;
        const float a1 = bw * bh;

        // best_iou < 0.5  <=>  for all n: 3*inter < a1 + a2   (division-free)
        bool neg = true;
        const float* __restrict__ tg = target + (size_t)b * 100;  // 20 * 5
        #pragma unroll 4
        for (int n = 0; n < 20; n++) {
            const float tx = tg[n * 5 + 0];
            const float ty = tg[n * 5 + 1];
            const float tw = tg[n * 5 + 2];
            const float th = tg[n * 5 + 3];
            const float hw = 0.5f * tw, hh = 0.5f * th;
            float iw = fminf(b1maxx, tx + hw) - fmaxf(b1minx, tx - hw);
            float ih = fminf(b1maxy, ty + hh) - fmaxf(b1miny, ty - hh);
            iw = fmaxf(iw, 0.f);
            ih = fmaxf(ih, 0.f);
            const float inter = iw * ih;
            neg = neg && (3.f * inter < a1 + tw * th);
        }
        const float negf = neg ? 1.f : 0.f;

        // ---- conf loss ----
        const float conf_bce = sp4 + (1.f - om) * r4;
        loss += (om + (1.f - om) * negf) * conf_bce;

        // ---- class loss: sum softplus via log-of-product in groups of 8 ----
        float cls = 0.f;
        #pragma unroll
        for (int g = 0; g < 10; g++) {
            float prod = 1.f;
            float lin = 0.f;
            #pragma unroll
            for (int j = 0; j < 8; j++) {
                const int c = 5 + g * 8 + j;
                const float r = p[c * cs];
                const float t = t85[c];
                prod *= (1.f + __expf(-r));
                lin += (1.f - t) * r;
            }
            cls += __logf(prod) + lin;
        }
        loss += om * cls;
    }

    // ---- block reduction ----
    __shared__ float ws[8];
    const unsigned m = 0xFFFFFFFFu;
    #pragma unroll
    for (int o = 16; o > 0; o >>= 1) loss += __shfl_down_sync(m, loss, o);
    const int lane = threadIdx.x & 31;
    const int wid  = threadIdx.x >> 5;
    if (lane == 0) ws[wid] = loss;
    __syncthreads();
    if (wid == 0) {
        float v = (lane < 8) ? ws[lane] : 0.f;
        #pragma unroll
        for (int o = 4; o > 0; o >>= 1) v += __shfl_down_sync(m, v, o);
        if (lane == 0) atomicAdd(&g_acc, (double)v);
    }
}

static void launch_layer(const float* pred, const float* ytr, const float* tgt,
                         int B, int H, int W,
                         const float* anchors_w, const float* anchors_h)
{
    AnchorParams ap;
    for (int a = 0; a < 3; a++) {
        ap.s_aw[a] = anchors_w[a] / 416.f;
        ap.s_ah[a] = anchors_h[a] / 416.f;
        ap.i_aw[a] = 416.f / anchors_w[a];
        ap.i_ah[a] = 416.f / anchors_h[a];
    }
    const int total = B * 3 * H * W;
    const int blocks = (total + 255) / 256;
    yolo_layer_kernel<<<blocks, 256>>>(pred, ytr, tgt, B, H, W,
                                       1.f / (float)W, 1.f / (float)H, ap);
}

extern "C" void kernel_launch(void* const* d_in, const int* in_sizes, int n_in,
                              void* d_out, int out_size)
{
    const float *p0, *p1, *p2, *t0, *t1, *t2;
    if (in_sizes[1] == in_sizes[0]) {
        // interleaved order: y_pred0, y_true0, y_pred1, y_true1, y_pred2, y_true2, target
        p0 = (const float*)d_in[0]; t0 = (const float*)d_in[1];
        p1 = (const float*)d_in[2]; t1 = (const float*)d_in[3];
        p2 = (const float*)d_in[4]; t2 = (const float*)d_in[5];
    } else {
        // grouped order: y_pred0..2, y_true0..2, target
        p0 = (const float*)d_in[0]; p1 = (const float*)d_in[1]; p2 = (const float*)d_in[2];
        t0 = (const float*)d_in[3]; t1 = (const float*)d_in[4]; t2 = (const float*)d_in[5];
    }
    const float* tgt = (const float*)d_in[6];
    const int B = in_sizes[6] / 100;  // target is (B, 20, 5)

    zero_kernel<<<1, 1>>>();

    // ANCHOR_MASK[0] = [6,7,8] for 13x13; [3,4,5] for 26x26; [0,1,2] for 52x52
    const float aw0[3] = {116.f, 156.f, 373.f}, ah0[3] = {90.f, 198.f, 326.f};
    const float aw1[3] = {30.f, 62.f, 59.f},    ah1[3] = {61.f, 45.f, 119.f};
    const float aw2[3] = {10.f, 16.f, 33.f},    ah2[3] = {13.f, 30.f, 23.f};

    launch_layer(p0, t0, tgt, B, 13, 13, aw0, ah0);
    launch_layer(p1, t1, tgt, B, 26, 26, aw1, ah1);
    launch_layer(p2, t2, tgt, B, 52, 52, aw2, ah2);

    final_kernel<<<1, 1>>>((float*)d_out);
}

// round 2
// speedup vs baseline: 1.3406x; 1.3406x over previous
#include <cuda_runtime.h>

// Persistent device state (statically initialized; last block resets for next replay).
__device__ double g_acc = 0.0;
__device__ unsigned int g_done = 0;

struct LayerParams {
    const float* pred;
    const float* ytr;
    int nblocks;
    int ncells;      // B*3*G*G
    float s_aw[3], s_ah[3], i_aw[3], i_ah[3];
};

struct KParams {
    LayerParams L[3];
    const float* target;
    float* out;
    int totalBlocks;
};

template<int G>
__device__ __forceinline__ float cell_loss(const float* __restrict__ pred,
                                           const float* __restrict__ t85,
                                           const float* __restrict__ target,
                                           int idx, const LayerParams& L)
{
    constexpr int cs = G * G;
    constexpr float invG = 1.f / (float)G;
    const int x = idx % G;
    const int y = (idx / G) % G;
    const int a = (idx / cs) % 3;
    const int b = idx / (3 * cs);

    const float* __restrict__ p = pred + ((size_t)(b * 255 + a * 85) * G + y) * G + x;
    const float s_aw = L.s_aw[a], s_ah = L.s_ah[a];
    const float i_aw = L.i_aw[a], i_ah = L.i_ah[a];

    const float r0 = p[0];
    const float r1 = p[cs];
    const float r2 = p[2 * cs];
    const float r3 = p[3 * cs];
    const float r4 = p[4 * cs];
    const float t0 = t85[0], t1 = t85[1], t2 = t85[2], t3 = t85[3], om = t85[4];

    const float gx = (float)x, gy = (float)y;
    float loss = 0.f;

    // bce(sigmoid(r), t) = softplus(-r) + (1-t)*r ;  softplus(-r) = log(1+exp(-r))
    const float e0 = __expf(-r0), e1 = __expf(-r1), e4 = __expf(-r4);
    const float sp0 = __logf(1.f + e0);
    const float sp1 = __logf(1.f + e1);
    const float sp4 = __logf(1.f + e4);

    // ---- xy loss ----  (ref: true_xy = y_true[...,0:2]*[h,w] - grid_xy)
    const float truex = t0 * (float)G - gx;
    const float truey = t1 * (float)G - gy;
    const float bce_x = sp0 + (1.f - truex) * r0;
    const float bce_y = sp1 + (1.f - truey) * r1;
    const float ls = 2.f - t2 * t3;
    loss += om * ls * (bce_x + bce_y);

    // ---- wh loss ----
    float twh = __logf(t2 * i_aw);
    float thh = __logf(t3 * i_ah);
    if (!(om > 0.f)) { twh = 0.f; thh = 0.f; }
    const float dw = r2 - twh, dh = r3 - thh;
    loss += om * ls * 0.5f * (dw * dw + dh * dh);

    // ---- predicted box for IoU ----
    const float sx = __fdividef(1.f, 1.f + e0);
    const float sy = __fdividef(1.f, 1.f + e1);
    const float bx = (sx + gx) * invG;
    const float by = (sy + gy) * invG;
    const float bw = __expf(r2) * s_aw;
    const float bh = __expf(r3) * s_ah;
    const float b1minx = bx - 0.5f * bw, b1maxx = bx + 0.5f * bw;
    const float b1miny = by - 0.5f * bh, b1maxy = by + 0.5f * bh;
    const float a1 = bw * bh;

    // best_iou < 0.5  <=>  for all n: 3*inter < a1 + a2  (division-free)
    bool neg = true;
    const float* __restrict__ tg = target + (size_t)b * 100;
    #pragma unroll 4
    for (int n = 0; n < 20; n++) {
        const float tx = tg[n * 5 + 0];
        const float ty = tg[n * 5 + 1];
        const float tw = tg[n * 5 + 2];
        const float th = tg[n * 5 + 3];
        const float hw = 0.5f * tw, hh = 0.5f * th;
        float iw = fminf(b1maxx, tx + hw) - fmaxf(b1minx, tx - hw);
        float ih = fminf(b1maxy, ty + hh) - fmaxf(b1miny, ty - hh);
        iw = fmaxf(iw, 0.f);
        ih = fmaxf(ih, 0.f);
        const float inter = iw * ih;
        neg = neg && (3.f * inter < a1 + tw * th);
    }
    const float negf = neg ? 1.f : 0.f;

    // ---- conf loss ----
    const float conf_bce = sp4 + (1.f - om) * r4;
    loss += (om + (1.f - om) * negf) * conf_bce;

    // ---- class loss: softplus sum via log-of-product in groups of 8 ----
    float cls = 0.f;
    #pragma unroll
    for (int g = 0; g < 10; g++) {
        float prod = 1.f;
        float lin = 0.f;
        #pragma unroll
        for (int j = 0; j < 8; j++) {
            const int c = 5 + g * 8 + j;
            const float r = p[(size_t)c * cs];
            const float t = t85[c];
            prod *= (1.f + __expf(-r));
            lin += (1.f - t) * r;
        }
        cls += __logf(prod) + lin;
    }
    loss += om * cls;
    return loss;
}

__global__ __launch_bounds__(128)
void yolo_fused_kernel(KParams kp)
{
    __shared__ float sm[128 * 85];
    __shared__ float ws[4];

    int lb = blockIdx.x;
    int layer = 0;
    if (lb >= kp.L[0].nblocks) {
        lb -= kp.L[0].nblocks; layer = 1;
        if (lb >= kp.L[1].nblocks) { lb -= kp.L[1].nblocks; layer = 2; }
    }
    const LayerParams& L = kp.L[layer];
    const int cellBase = lb * 128;
    const int ncells = min(128, L.ncells - cellBase);

    // ---- stage this block's y_true slab (coalesced float4) ----
    {
        const float* __restrict__ src = L.ytr + (size_t)cellBase * 85;
        const int nf = ncells * 85;
        const int nf4 = nf >> 2;
        const float4* __restrict__ src4 = (const float4*)src;
        float4* sm4 = (float4*)sm;
        for (int i = threadIdx.x; i < nf4; i += 128) sm4[i] = src4[i];
        for (int i = (nf4 << 2) + threadIdx.x; i < nf; i += 128) sm[i] = src[i];
    }
    __syncthreads();

    float loss = 0.f;
    if (threadIdx.x < ncells) {
        const int idx = cellBase + threadIdx.x;
        const float* t85 = sm + threadIdx.x * 85;
        if (layer == 0)      loss = cell_loss<13>(L.pred, t85, kp.target, idx, L);
        else if (layer == 1) loss = cell_loss<26>(L.pred, t85, kp.target, idx, L);
        else                 loss = cell_loss<52>(L.pred, t85, kp.target, idx, L);
    }

    // ---- block reduction ----
    const unsigned m = 0xFFFFFFFFu;
    #pragma unroll
    for (int o = 16; o > 0; o >>= 1) loss += __shfl_down_sync(m, loss, o);
    const int lane = threadIdx.x & 31;
    const int wid  = threadIdx.x >> 5;
    if (lane == 0) ws[wid] = loss;
    __syncthreads();
    if (threadIdx.x == 0) {
        float bs = ws[0] + ws[1] + ws[2] + ws[3];
        atomicAdd(&g_acc, (double)bs);
        __threadfence();
        const unsigned done = atomicAdd(&g_done, 1u);
        if (done == (unsigned)(kp.totalBlocks - 1)) {
            __threadfence();
            kp.out[0] = (float)g_acc;
            g_acc = 0.0;       // reset for next graph replay
            g_done = 0;
        }
    }
}

static void fill_anchors(LayerParams& L, const float* aw, const float* ah)
{
    for (int a = 0; a < 3; a++) {
        L.s_aw[a] = aw[a] / 416.f;
        L.s_ah[a] = ah[a] / 416.f;
        L.i_aw[a] = 416.f / aw[a];
        L.i_ah[a] = 416.f / ah[a];
    }
}

extern "C" void kernel_launch(void* const* d_in, const int* in_sizes, int n_in,
                              void* d_out, int out_size)
{
    const float *p0, *p1, *p2, *t0, *t1, *t2;
    if (in_sizes[1] == in_sizes[0]) {
        // interleaved: y_pred0, y_true0, y_pred1, y_true1, y_pred2, y_true2, target
        p0 = (const float*)d_in[0]; t0 = (const float*)d_in[1];
        p1 = (const float*)d_in[2]; t1 = (const float*)d_in[3];
        p2 = (const float*)d_in[4]; t2 = (const float*)d_in[5];
    } else {
        // grouped: y_pred0..2, y_true0..2, target
        p0 = (const float*)d_in[0]; p1 = (const float*)d_in[1]; p2 = (const float*)d_in[2];
        t0 = (const float*)d_in[3]; t1 = (const float*)d_in[4]; t2 = (const float*)d_in[5];
    }
    const int B = in_sizes[6] / 100;   // target is (B, 20, 5)

    KParams kp;
    kp.target = (const float*)d_in[6];
    kp.out    = (float*)d_out;

    const int grids[3] = {13, 26, 52};
    const float aw[3][3] = {{116.f, 156.f, 373.f}, {30.f, 62.f, 59.f}, {10.f, 16.f, 33.f}};
    const float ah[3][3] = {{90.f, 198.f, 326.f},  {61.f, 45.f, 119.f}, {13.f, 30.f, 23.f}};
    const float* preds[3] = {p0, p1, p2};
    const float* trues[3] = {t0, t1, t2};

    int total = 0;
    for (int l = 0; l < 3; l++) {
        LayerParams& L = kp.L[l];
        L.pred = preds[l];
        L.ytr  = trues[l];
        L.ncells = B * 3 * grids[l] * grids[l];
        L.nblocks = (L.ncells + 127) / 128;
        fill_anchors(L, aw[l], ah[l]);
        total += L.nblocks;
    }
    kp.totalBlocks = total;

    yolo_fused_kernel<<<total, 128>>>(kp);
}